// round 1
// baseline (speedup 1.0000x reference)
#include <cuda_runtime.h>
#include <cstdint>

// Problem constants
#define NIMG 64
#define DIM  256
#define HW   1024          // 32*32
#define M    65536         // NIMG*HW vectors
#define K    1024          // codebook size
#define ZQ_ELEMS 16777216  // 64*256*32*32

// Scratch (static device arrays — no allocation)
__device__ float  g_enorm[K];
__device__ float  g_znorm[M];
__device__ int    g_idx[M];
__device__ double g_loss;

// ---------------- packed f32x2 helpers ----------------
__device__ __forceinline__ unsigned long long pack2(float v) {
    unsigned long long r; unsigned u = __float_as_uint(v);
    asm("mov.b64 %0, {%1, %1};" : "=l"(r) : "r"(u));
    return r;
}
__device__ __forceinline__ void fma2(unsigned long long &d,
                                     unsigned long long a,
                                     unsigned long long b) {
    asm("fma.rn.f32x2 %0, %1, %2, %0;" : "+l"(d) : "l"(a), "l"(b));
}
__device__ __forceinline__ void unpack2(unsigned long long p, float &lo, float &hi) {
    unsigned a, b;
    asm("mov.b64 {%0, %1}, %2;" : "=r"(a), "=r"(b) : "l"(p));
    lo = __uint_as_float(a); hi = __uint_as_float(b);
}

// ---------------- init ----------------
__global__ void k_init() { g_loss = 0.0; }

// ---------------- ||e_k||^2 : 1024 blocks x 32 threads ----------------
__global__ void k_enorm(const float* __restrict__ emb) {
    int k = blockIdx.x;
    int lid = threadIdx.x;
    const float* p = emb + (size_t)k * DIM + lid * 8;
    float4 a = *(const float4*)p;
    float4 b = *(const float4*)(p + 4);
    float s = a.x*a.x; s = fmaf(a.y,a.y,s); s = fmaf(a.z,a.z,s); s = fmaf(a.w,a.w,s);
    s = fmaf(b.x,b.x,s); s = fmaf(b.y,b.y,s); s = fmaf(b.z,b.z,s); s = fmaf(b.w,b.w,s);
    #pragma unroll
    for (int off = 16; off; off >>= 1)
        s += __shfl_xor_sync(0xffffffffu, s, off);
    if (lid == 0) g_enorm[k] = s;
}

// ---------------- ||z_m||^2 : grid (8, 64) x 128 threads ----------------
__global__ void k_znorm(const float* __restrict__ z) {
    int n  = blockIdx.y;
    int hw = blockIdx.x * 128 + threadIdx.x;
    const float* zp = z + ((size_t)n * DIM << 10) + hw;
    float s = 0.f;
    #pragma unroll 8
    for (int d = 0; d < DIM; d++) {
        float v = zp[(size_t)d << 10];
        s = fmaf(v, v, s);
    }
    g_znorm[(n << 10) + hw] = s;
}

// ---------------- argmin GEMM ----------------
#define TM 64
#define TK 128
#define BD 32
#define ZS_STRIDE 68
#define ES_STRIDE 132

__global__ void __launch_bounds__(256)
k_argmin(const float* __restrict__ z, const float* __restrict__ emb,
         float* __restrict__ out_idx) {
    __shared__ float zs[BD][ZS_STRIDE];
    __shared__ float es[BD][ES_STRIDE];
    __shared__ float s_enorm[TK];
    __shared__ float s_znorm[TM];

    const int tid = threadIdx.x;
    const int m0  = blockIdx.x * TM;
    const int n   = m0 >> 10;
    const int hw0 = m0 & (HW - 1);
    const float* zbase = z + ((size_t)n * DIM << 10) + hw0;

    const int mg = tid >> 4;   // 0..15  -> m frag = 4*mg
    const int kg = tid & 15;   // 0..15  -> k frag = 8*kg

    if (tid < TM) s_znorm[tid] = g_znorm[m0 + tid];

    float bestd[4]; int besti[4];
    #pragma unroll
    for (int i = 0; i < 4; i++) { bestd[i] = 3.4e38f; besti[i] = 0; }

    for (int kc = 0; kc < K; kc += TK) {
        unsigned long long acc[4][4];
        #pragma unroll
        for (int i = 0; i < 4; i++)
            #pragma unroll
            for (int p = 0; p < 4; p++) acc[i][p] = 0ull;

        if (tid < TK) s_enorm[tid] = g_enorm[kc + tid];

        for (int d0 = 0; d0 < DIM; d0 += BD) {
            // load z tile: zs[dd][mm]
            {
                int dd = tid >> 3, mb = (tid & 7) << 3;
                const float* gp = zbase + ((size_t)(d0 + dd) << 10) + mb;
                float4 a = *(const float4*)gp;
                float4 b = *(const float4*)(gp + 4);
                *(float4*)&zs[dd][mb]     = a;
                *(float4*)&zs[dd][mb + 4] = b;
            }
            // load e tile (transpose): es[dd][kk]
            {
                int kk = tid >> 1, db = (tid & 1) << 4;
                const float* ep = emb + (size_t)(kc + kk) * DIM + d0 + db;
                float4 v0 = *(const float4*)(ep);
                float4 v1 = *(const float4*)(ep + 4);
                float4 v2 = *(const float4*)(ep + 8);
                float4 v3 = *(const float4*)(ep + 12);
                es[db+ 0][kk]=v0.x; es[db+ 1][kk]=v0.y; es[db+ 2][kk]=v0.z; es[db+ 3][kk]=v0.w;
                es[db+ 4][kk]=v1.x; es[db+ 5][kk]=v1.y; es[db+ 6][kk]=v1.z; es[db+ 7][kk]=v1.w;
                es[db+ 8][kk]=v2.x; es[db+ 9][kk]=v2.y; es[db+10][kk]=v2.z; es[db+11][kk]=v2.w;
                es[db+12][kk]=v3.x; es[db+13][kk]=v3.y; es[db+14][kk]=v3.z; es[db+15][kk]=v3.w;
            }
            __syncthreads();
            #pragma unroll
            for (int dd = 0; dd < BD; dd++) {
                float4 zf = *(const float4*)&zs[dd][mg << 2];
                const float* er = &es[dd][kg << 3];
                ulonglong2 ea = *(const ulonglong2*)er;
                ulonglong2 eb = *(const ulonglong2*)(er + 4);
                unsigned long long zz;
                zz = pack2(zf.x);
                fma2(acc[0][0], zz, ea.x); fma2(acc[0][1], zz, ea.y);
                fma2(acc[0][2], zz, eb.x); fma2(acc[0][3], zz, eb.y);
                zz = pack2(zf.y);
                fma2(acc[1][0], zz, ea.x); fma2(acc[1][1], zz, ea.y);
                fma2(acc[1][2], zz, eb.x); fma2(acc[1][3], zz, eb.y);
                zz = pack2(zf.z);
                fma2(acc[2][0], zz, ea.x); fma2(acc[2][1], zz, ea.y);
                fma2(acc[2][2], zz, eb.x); fma2(acc[2][3], zz, eb.y);
                zz = pack2(zf.w);
                fma2(acc[3][0], zz, ea.x); fma2(acc[3][1], zz, ea.y);
                fma2(acc[3][2], zz, eb.x); fma2(acc[3][3], zz, eb.y);
            }
            __syncthreads();
        }

        // epilogue: distances + argmin (replicating reference fp32 rounding:
        // d = fl(fl(znorm - 2*dot) + enorm), first-index tie-break)
        #pragma unroll
        for (int i = 0; i < 4; i++) {
            float zn = s_znorm[(mg << 2) + i];
            float bd = 3.4e38f; int bi = 0;
            #pragma unroll
            for (int p = 0; p < 4; p++) {
                float lo, hi; unpack2(acc[i][p], lo, hi);
                int kk = (kg << 3) + (p << 1);
                float t1 = zn - 2.0f * lo;
                float dl = t1 + s_enorm[kk];
                float t2 = zn - 2.0f * hi;
                float dh = t2 + s_enorm[kk + 1];
                if (dl < bd) { bd = dl; bi = kc + kk; }
                if (dh < bd) { bd = dh; bi = kc + kk + 1; }
            }
            #pragma unroll
            for (int off = 8; off; off >>= 1) {
                float od = __shfl_xor_sync(0xffffffffu, bd, off);
                int   oi = __shfl_xor_sync(0xffffffffu, bi, off);
                if (od < bd || (od == bd && oi < bi)) { bd = od; bi = oi; }
            }
            if (bd < bestd[i]) { bestd[i] = bd; besti[i] = bi; }
        }
        __syncthreads();
    }

    if ((tid & 15) == 0) {
        #pragma unroll
        for (int i = 0; i < 4; i++) {
            int m = m0 + (mg << 2) + i;
            g_idx[m]   = besti[i];
            out_idx[m] = (float)besti[i];
        }
    }
}

// ---------------- output + loss: 16384 blocks x 256 threads ----------------
__global__ void __launch_bounds__(256)
k_out(const float* __restrict__ z, const float* __restrict__ emb,
      float* __restrict__ out_zq) {
    int t   = blockIdx.x * 256 + threadIdx.x;   // 4,194,304 threads
    int hw  = t & 1023;
    int rest = t >> 10;
    int db  = (rest & 63) << 2;                 // d block of 4
    int n   = rest >> 6;

    int idx = g_idx[(n << 10) + hw];
    float4 e = *(const float4*)&emb[(size_t)idx * DIM + db];

    size_t zb = (((size_t)n * DIM + db) << 10) + hw;
    float z0 = z[zb], z1 = z[zb + 1024], z2 = z[zb + 2048], z3 = z[zb + 3072];

    out_zq[zb]        = z0 + (e.x - z0);
    out_zq[zb + 1024] = z1 + (e.y - z1);
    out_zq[zb + 2048] = z2 + (e.z - z2);
    out_zq[zb + 3072] = z3 + (e.w - z3);

    float d0 = z0 - e.x, d1 = z1 - e.y, d2 = z2 - e.z, d3 = z3 - e.w;
    float sq = d0*d0 + d1*d1 + d2*d2 + d3*d3;

    #pragma unroll
    for (int off = 16; off; off >>= 1)
        sq += __shfl_xor_sync(0xffffffffu, sq, off);

    __shared__ float wsum[8];
    int wid = threadIdx.x >> 5, lid = threadIdx.x & 31;
    if (lid == 0) wsum[wid] = sq;
    __syncthreads();
    if (threadIdx.x == 0) {
        float s = 0.f;
        #pragma unroll
        for (int w = 0; w < 8; w++) s += wsum[w];
        atomicAdd(&g_loss, (double)s);
    }
}

// ---------------- finalize loss ----------------
__global__ void k_fin(float* __restrict__ out_loss) {
    float m = (float)(g_loss / (double)ZQ_ELEMS);
    out_loss[0] = 0.02f * m + m;   // commitment + codebook (forward value)
}

extern "C" void kernel_launch(void* const* d_in, const int* in_sizes, int n_in,
                              void* d_out, int out_size) {
    const float* z   = (const float*)d_in[0];
    const float* emb = (const float*)d_in[1];
    float* out      = (float*)d_out;
    float* out_zq   = out;                       // 16,777,216
    float* out_idx  = out + ZQ_ELEMS;            // 65,536
    float* out_loss = out + ZQ_ELEMS + M;        // 1

    k_init  <<<1, 1>>>();
    k_enorm <<<K, 32>>>(emb);
    k_znorm <<<dim3(8, NIMG), 128>>>(z);
    k_argmin<<<M / TM, 256>>>(z, emb, out_idx);
    k_out   <<<ZQ_ELEMS / (256 * 4), 256>>>(z, emb, out_zq);
    k_fin   <<<1, 1>>>(out_loss);
}

// round 5
// speedup vs baseline: 1.5562x; 1.5562x over previous
#include <cuda_runtime.h>
#include <cuda_fp16.h>
#include <cstdint>

#define NIMG 64
#define DIM  256
#define HW   1024
#define MTOT 65536
#define KCODES 1024
#define ZQ_ELEMS 16777216

__device__ float  g_enorm[KCODES];
__device__ int    g_idx[MTOT];
__device__ int    g_cand[MTOT * 4];
__device__ double g_loss;
__device__ __half g_ehi[KCODES * DIM];   // split of 1024*emb
__device__ __half g_elo[KCODES * DIM];

// ---------------- smem layout (bytes) ----------------
#define ZH_OFF 0                  // 128 rows x 264 halves (528B stride)
#define ZL_OFF 67584
#define EB_OFF 135168             // 2 x (128 codes x 72 halves, 144B stride)
#define EB_SZ  18432
#define ZN_OFF 172032             // 128 f32
#define EN_OFF 172544             // 1024 f32
#define CD_OFF 176640             // 128 x 4 f32 cand dists (also znorm tmp)
#define CI_OFF 178688             // 128 x 4 i32 cand idx
#define SMEM_ARG 180736

__device__ __forceinline__ uint32_t smem_u32(const void* p) {
    uint32_t a;
    asm("{ .reg .u64 t; cvta.to.shared.u64 t, %1; cvt.u32.u64 %0, t; }" : "=r"(a) : "l"(p));
    return a;
}
#define LDSM4(r0,r1,r2,r3,addr) \
    asm volatile("ldmatrix.sync.aligned.m8n8.x4.shared.b16 {%0,%1,%2,%3}, [%4];" \
                 : "=r"(r0), "=r"(r1), "=r"(r2), "=r"(r3) : "r"(addr))
#define MMA_F16(c, a0,a1,a2,a3, b0,b1) \
    asm volatile("mma.sync.aligned.m16n8k16.row.col.f32.f16.f16.f32 " \
                 "{%0,%1,%2,%3}, {%4,%5,%6,%7}, {%8,%9}, {%0,%1,%2,%3};" \
                 : "+f"((c)[0]), "+f"((c)[1]), "+f"((c)[2]), "+f"((c)[3]) \
                 : "r"(a0), "r"(a1), "r"(a2), "r"(a3), "r"(b0), "r"(b1))

// sorted-insert into length-4 top list, (dist, idx) lexicographic
__device__ __forceinline__ void ins4(float* td, int* ti, float d, int i) {
    if (d < td[3] || (d == td[3] && i < ti[3])) {
        td[3] = d; ti[3] = i;
        #pragma unroll
        for (int k = 3; k > 0; k--) {
            bool sw = td[k] < td[k-1] || (td[k] == td[k-1] && ti[k] < ti[k-1]);
            if (sw) {
                float tf = td[k]; td[k] = td[k-1]; td[k-1] = tf;
                int   tt = ti[k]; ti[k] = ti[k-1]; ti[k-1] = tt;
            }
        }
    }
}

// ==================== small kernels ====================
__global__ void k_init() { g_loss = 0.0; }

// identical to round-1 (bit-matching enorm values)
__global__ void k_enorm(const float* __restrict__ emb) {
    int k = blockIdx.x, lid = threadIdx.x;
    const float* p = emb + (size_t)k * DIM + lid * 8;
    float4 a = *(const float4*)p;
    float4 b = *(const float4*)(p + 4);
    float s = a.x*a.x; s = fmaf(a.y,a.y,s); s = fmaf(a.z,a.z,s); s = fmaf(a.w,a.w,s);
    s = fmaf(b.x,b.x,s); s = fmaf(b.y,b.y,s); s = fmaf(b.z,b.z,s); s = fmaf(b.w,b.w,s);
    #pragma unroll
    for (int off = 16; off; off >>= 1) s += __shfl_xor_sync(0xffffffffu, s, off);
    if (lid == 0) g_enorm[k] = s;
}

__global__ void k_esplit(const float* __restrict__ emb) {
    int t = blockIdx.x * 256 + threadIdx.x;
    #pragma unroll
    for (int i = 0; i < 4; i++) {
        int id = t * 4 + i;
        float v = emb[id] * 1024.0f;
        __half hi = __float2half_rn(v);
        __half lo = __float2half_rn(v - __half2float(hi));
        g_ehi[id] = hi;
        g_elo[id] = lo;
    }
}

// ==================== phase A: candidate search via mma.sync fp16 x3 ====================
__device__ __forceinline__ void issue_chunk(uint32_t sb, int j, int tid) {
    const int nt = j / 12, rem = j % 12, term = rem >> 2, kc = rem & 3;
    const __half* base = (term == 2) ? g_elo : g_ehi;
    const uint32_t dst0 = sb + EB_OFF + (uint32_t)(j & 1) * EB_SZ;
    #pragma unroll
    for (int i = 0; i < 4; i++) {
        int g = tid * 4 + i;
        int code = g >> 3, u = g & 7;
        uint32_t dst = dst0 + (uint32_t)(code * 144 + u * 16);
        uint64_t src = (uint64_t)__cvta_generic_to_global(
            base + (((size_t)(nt * 128 + code)) << 8) + kc * 64 + u * 8);
        asm volatile("cp.async.cg.shared.global [%0], [%1], 16;"
                     :: "r"(dst), "l"(src) : "memory");
    }
    asm volatile("cp.async.commit_group;" ::: "memory");
}

__global__ void __launch_bounds__(256, 1)
k_argmin_mma(const float* __restrict__ z) {
    extern __shared__ char smem[];
    const uint32_t sb = smem_u32(smem);
    const int tid = threadIdx.x;
    const int lane = tid & 31;
    const int warp = tid >> 5;
    const int wm = warp & 3;        // m-group: rows wm*32..+31
    const int wn = warp >> 2;       // n-group: cols wn*64..+63 within code tile

    const int m0 = blockIdx.x * 128;
    const int n_img = m0 >> 10;
    const int hw0 = m0 & (HW - 1);

    issue_chunk(sb, 0, tid);

    // ---------- phase 1: z load + fp16 split + approx znorm ----------
    const float* zbase = z + (size_t)n_img * DIM * HW + hw0;
    {
        const int row = tid & 127;
        const int d0  = tid >> 7;
        __half* zh = (__half*)(smem + ZH_OFF);
        __half* zl = (__half*)(smem + ZL_OFF);
        float zn = 0.f;
        #pragma unroll 8
        for (int i = 0; i < 128; i++) {
            int d = 2 * i + d0;
            float v = zbase[((size_t)d << 10) + row];
            zn = fmaf(v, v, zn);
            __half hi = __float2half_rn(v);
            __half lo = __float2half_rn(v - __half2float(hi));
            zh[row * 264 + d] = hi;
            zl[row * 264 + d] = lo;
        }
        float* tmp = (float*)(smem + CD_OFF);   // 256 f32 scratch
        tmp[tid] = zn;
        float* se = (float*)(smem + EN_OFF);
        #pragma unroll
        for (int i = 0; i < 4; i++) se[tid + 256 * i] = g_enorm[tid + 256 * i];
        __syncthreads();
        if (tid < 128)
            ((float*)(smem + ZN_OFF))[tid] = tmp[tid] + tmp[tid + 128];
    }

    // ---------- phase 2: main loop ----------
    float acc[2][8][4];
    float td[2][2][4]; int ti[2][2][4];
    #pragma unroll
    for (int a = 0; a < 2; a++)
        #pragma unroll
        for (int b = 0; b < 2; b++)
            #pragma unroll
            for (int k = 0; k < 4; k++) { td[a][b][k] = 3.4e38f; ti[a][b][k] = 0x7fffffff; }

    const float* s_zn = (const float*)(smem + ZN_OFF);
    const float* s_en = (const float*)(smem + EN_OFF);

    for (int j = 0; j < 96; j++) {
        const int nt = j / 12, rem = j % 12, term = rem >> 2, kc = rem & 3;

        asm volatile("cp.async.wait_group 0;" ::: "memory");
        __syncthreads();
        if (j < 95) issue_chunk(sb, j + 1, tid);

        if (rem == 0) {
            #pragma unroll
            for (int mt = 0; mt < 2; mt++)
                #pragma unroll
                for (int q = 0; q < 8; q++)
                    #pragma unroll
                    for (int c = 0; c < 4; c++) acc[mt][q][c] = 0.f;
        }

        const uint32_t abase = sb + ((term == 1) ? ZL_OFF : ZH_OFF);
        const uint32_t bbase = sb + EB_OFF + (uint32_t)(j & 1) * EB_SZ;
        const uint32_t arow  = (uint32_t)(wm * 32 + (lane & 15)) * 528u;
        const uint32_t alanec = (uint32_t)((lane >> 4) * 16);
        const uint32_t brow0 = (uint32_t)(wn * 64 + (lane & 15)) * 144u;
        #pragma unroll
        for (int ks = 0; ks < 4; ks++) {
            const uint32_t kbyte = (uint32_t)(kc * 128 + ks * 32) + alanec;
            uint32_t a0[4], a1[4];
            LDSM4(a0[0],a0[1],a0[2],a0[3], abase + arow + kbyte);
            LDSM4(a1[0],a1[1],a1[2],a1[3], abase + arow + 16u*528u + kbyte);
            const uint32_t bcol = (uint32_t)(ks * 32) + alanec;
            uint32_t br[4][4];
            #pragma unroll
            for (int q = 0; q < 4; q++)
                LDSM4(br[q][0],br[q][1],br[q][2],br[q][3],
                      bbase + brow0 + (uint32_t)(q * 16 * 144) + bcol);
            #pragma unroll
            for (int q = 0; q < 4; q++) {
                MMA_F16(acc[0][2*q],   a0[0],a0[1],a0[2],a0[3], br[q][0], br[q][2]);
                MMA_F16(acc[0][2*q+1], a0[0],a0[1],a0[2],a0[3], br[q][1], br[q][3]);
                MMA_F16(acc[1][2*q],   a1[0],a1[1],a1[2],a1[3], br[q][0], br[q][2]);
                MMA_F16(acc[1][2*q+1], a1[0],a1[1],a1[2],a1[3], br[q][1], br[q][3]);
            }
        }

        if (rem == 11) {
            // fused epilogue: collect top-4 candidates per owned row
            #pragma unroll
            for (int mt = 0; mt < 2; mt++) {
                #pragma unroll
                for (int h = 0; h < 2; h++) {
                    const int row = wm * 32 + mt * 16 + h * 8 + (lane >> 2);
                    const float zn = s_zn[row];
                    #pragma unroll
                    for (int q = 0; q < 8; q++) {
                        #pragma unroll
                        for (int c = 0; c < 2; c++) {
                            const int col = nt * 128 + wn * 64 + q * 8 + (lane & 3) * 2 + c;
                            const float dist =
                                (zn - acc[mt][q][2*h + c] * (1.0f/512.0f)) + s_en[col];
                            ins4(&td[mt][h][0], &ti[mt][h][0], dist, col);
                        }
                    }
                }
            }
        }
    }

    // ---------- candidate merge ----------
    // quad merge (lanes differing in bits 0,1 cover same rows, different cols)
    #pragma unroll
    for (int mt = 0; mt < 2; mt++)
        #pragma unroll
        for (int h = 0; h < 2; h++) {
            #pragma unroll
            for (int off = 1; off <= 2; off <<= 1) {
                float od[4]; int oi[4];
                #pragma unroll
                for (int k = 0; k < 4; k++) {
                    od[k] = __shfl_xor_sync(0xffffffffu, td[mt][h][k], off);
                    oi[k] = __shfl_xor_sync(0xffffffffu, ti[mt][h][k], off);
                }
                #pragma unroll
                for (int k = 0; k < 4; k++)
                    ins4(&td[mt][h][0], &ti[mt][h][0], od[k], oi[k]);
            }
        }

    float* cd = (float*)(smem + CD_OFF);
    int*   ci = (int*)(smem + CI_OFF);
    __syncthreads();   // scratch reuse safe + all epilogues done
    if (wn == 0 && (lane & 3) == 0) {
        #pragma unroll
        for (int mt = 0; mt < 2; mt++)
            #pragma unroll
            for (int h = 0; h < 2; h++) {
                int row = wm * 32 + mt * 16 + h * 8 + (lane >> 2);
                #pragma unroll
                for (int k = 0; k < 4; k++) { cd[row*4+k] = td[mt][h][k]; ci[row*4+k] = ti[mt][h][k]; }
            }
    }
    __syncthreads();
    if (wn == 1 && (lane & 3) == 0) {
        #pragma unroll
        for (int mt = 0; mt < 2; mt++)
            #pragma unroll
            for (int h = 0; h < 2; h++) {
                int row = wm * 32 + mt * 16 + h * 8 + (lane >> 2);
                #pragma unroll
                for (int k = 0; k < 4; k++)
                    ins4(&td[mt][h][0], &ti[mt][h][0], cd[row*4+k], ci[row*4+k]);
                #pragma unroll
                for (int k = 0; k < 4; k++)
                    g_cand[(m0 + row)*4 + k] = ti[mt][h][k];
            }
    }
}

// ==================== phase B: exact fp32 rescore (round-1 bit-exact formulation) ====================
__global__ void __launch_bounds__(256)
k_exact(const float* __restrict__ z, const float* __restrict__ emb,
        float* __restrict__ out_idx) {
    int row = blockIdx.x * 256 + threadIdx.x;
    int n_img = row >> 10, hw = row & 1023;
    const float* zp = z + (size_t)n_img * DIM * HW + hw;

    int4 cn = *(const int4*)&g_cand[row * 4];
    const float4* e0 = (const float4*)(emb + ((size_t)cn.x << 8));
    const float4* e1 = (const float4*)(emb + ((size_t)cn.y << 8));
    const float4* e2 = (const float4*)(emb + ((size_t)cn.z << 8));
    const float4* e3 = (const float4*)(emb + ((size_t)cn.w << 8));

    float a0 = 0.f, a1 = 0.f, a2 = 0.f, a3 = 0.f, zn = 0.f;
    #pragma unroll 4
    for (int d4 = 0; d4 < 64; d4++) {
        float4 v0 = e0[d4], v1 = e1[d4], v2 = e2[d4], v3 = e3[d4];
        float zv;
        zv = zp[(size_t)(d4*4 + 0) << 10];
        zn = fmaf(zv, zv, zn);
        a0 = fmaf(zv, v0.x, a0); a1 = fmaf(zv, v1.x, a1);
        a2 = fmaf(zv, v2.x, a2); a3 = fmaf(zv, v3.x, a3);
        zv = zp[(size_t)(d4*4 + 1) << 10];
        zn = fmaf(zv, zv, zn);
        a0 = fmaf(zv, v0.y, a0); a1 = fmaf(zv, v1.y, a1);
        a2 = fmaf(zv, v2.y, a2); a3 = fmaf(zv, v3.y, a3);
        zv = zp[(size_t)(d4*4 + 2) << 10];
        zn = fmaf(zv, zv, zn);
        a0 = fmaf(zv, v0.z, a0); a1 = fmaf(zv, v1.z, a1);
        a2 = fmaf(zv, v2.z, a2); a3 = fmaf(zv, v3.z, a3);
        zv = zp[(size_t)(d4*4 + 3) << 10];
        zn = fmaf(zv, zv, zn);
        a0 = fmaf(zv, v0.w, a0); a1 = fmaf(zv, v1.w, a1);
        a2 = fmaf(zv, v2.w, a2); a3 = fmaf(zv, v3.w, a3);
    }

    // d = fl(fl(zn - 2*dot) + enorm), min with lowest-index tie-break
    float bd; int bi;
    {
        float t = zn - 2.0f * a0; bd = t + g_enorm[cn.x]; bi = cn.x;
    }
    {
        float t = zn - 2.0f * a1; float d = t + g_enorm[cn.y];
        if (d < bd || (d == bd && cn.y < bi)) { bd = d; bi = cn.y; }
    }
    {
        float t = zn - 2.0f * a2; float d = t + g_enorm[cn.z];
        if (d < bd || (d == bd && cn.z < bi)) { bd = d; bi = cn.z; }
    }
    {
        float t = zn - 2.0f * a3; float d = t + g_enorm[cn.w];
        if (d < bd || (d == bd && cn.w < bi)) { bd = d; bi = cn.w; }
    }

    g_idx[row]   = bi;
    out_idx[row] = (float)bi;
}

// ==================== output + loss ====================
__global__ void __launch_bounds__(256)
k_out(const float* __restrict__ z, const float* __restrict__ emb,
      float* __restrict__ out_zq) {
    int t    = blockIdx.x * 256 + threadIdx.x;
    int hw   = t & 1023;
    int rest = t >> 10;
    int db   = (rest & 63) << 2;
    int n    = rest >> 6;

    int idx = g_idx[(n << 10) + hw];
    float4 e = *(const float4*)&emb[(size_t)idx * DIM + db];

    size_t zb = (((size_t)n * DIM + db) << 10) + hw;
    float z0 = z[zb], z1 = z[zb + 1024], z2 = z[zb + 2048], z3 = z[zb + 3072];

    out_zq[zb]        = z0 + (e.x - z0);
    out_zq[zb + 1024] = z1 + (e.y - z1);
    out_zq[zb + 2048] = z2 + (e.z - z2);
    out_zq[zb + 3072] = z3 + (e.w - z3);

    float d0 = z0 - e.x, d1 = z1 - e.y, d2 = z2 - e.z, d3 = z3 - e.w;
    float sq = d0*d0 + d1*d1 + d2*d2 + d3*d3;

    #pragma unroll
    for (int off = 16; off; off >>= 1) sq += __shfl_xor_sync(0xffffffffu, sq, off);

    __shared__ float wsum[8];
    int wid = threadIdx.x >> 5, lid = threadIdx.x & 31;
    if (lid == 0) wsum[wid] = sq;
    __syncthreads();
    if (threadIdx.x == 0) {
        float s = 0.f;
        #pragma unroll
        for (int w = 0; w < 8; w++) s += wsum[w];
        atomicAdd(&g_loss, (double)s);
    }
}

__global__ void k_fin(float* __restrict__ out_loss) {
    float m = (float)(g_loss / (double)ZQ_ELEMS);
    out_loss[0] = 0.02f * m + m;
}

extern "C" void kernel_launch(void* const* d_in, const int* in_sizes, int n_in,
                              void* d_out, int out_size) {
    const float* z   = (const float*)d_in[0];
    const float* emb = (const float*)d_in[1];
    float* out      = (float*)d_out;
    float* out_zq   = out;
    float* out_idx  = out + ZQ_ELEMS;
    float* out_loss = out + ZQ_ELEMS + MTOT;

    cudaFuncSetAttribute(k_argmin_mma, cudaFuncAttributeMaxDynamicSharedMemorySize, SMEM_ARG);

    k_init      <<<1, 1>>>();
    k_enorm     <<<KCODES, 32>>>(emb);
    k_esplit    <<<256, 256>>>(emb);
    k_argmin_mma<<<MTOT / 128, 256, SMEM_ARG>>>(z);
    k_exact     <<<MTOT / 256, 256>>>(z, emb, out_idx);
    k_out       <<<ZQ_ELEMS / (256 * 4), 256>>>(z, emb, out_zq);
    k_fin       <<<1, 1>>>(out_loss);
}

// round 6
// speedup vs baseline: 2.7467x; 1.7650x over previous
#include <cuda_runtime.h>
#include <cuda_fp16.h>
#include <cstdint>

#define NIMG 64
#define DIM  256
#define HW   1024
#define MTOT 65536
#define KCODES 1024
#define ZQ_ELEMS 16777216

__device__ float  g_enorm[KCODES];
__device__ int    g_idx[MTOT];
__device__ int    g_cand[MTOT * 4];
__device__ double g_loss;
__device__ __half g_ehi[KCODES * DIM];   // fp16(1024*emb)

// ---------------- smem layout (bytes), M-tile = 64 ----------------
#define ZH_OFF 0                  // 64 rows x 264 halves (528B stride)
#define EB_OFF 33792              // 3 x (128 codes x 72 halves, 144B stride)
#define EB_SZ  18432
#define EN_OFF 89088              // 1024 f32
#define ZN_OFF 93184              // 64 f32
#define CD_OFF 93440              // 64 x 4wn x 4 f32 (also znorm tmp 256 f32)
#define CI_OFF 97536              // 64 x 4wn x 4 i32
#define SMEM_ARG 101632

__device__ __forceinline__ uint32_t smem_u32(const void* p) {
    uint32_t a;
    asm("{ .reg .u64 t; cvta.to.shared.u64 t, %1; cvt.u32.u64 %0, t; }" : "=r"(a) : "l"(p));
    return a;
}
#define LDSM4(r0,r1,r2,r3,addr) \
    asm volatile("ldmatrix.sync.aligned.m8n8.x4.shared.b16 {%0,%1,%2,%3}, [%4];" \
                 : "=r"(r0), "=r"(r1), "=r"(r2), "=r"(r3) : "r"(addr))
#define MMA_F16(c, a0,a1,a2,a3, b0,b1) \
    asm volatile("mma.sync.aligned.m16n8k16.row.col.f32.f16.f16.f32 " \
                 "{%0,%1,%2,%3}, {%4,%5,%6,%7}, {%8,%9}, {%0,%1,%2,%3};" \
                 : "+f"((c)[0]), "+f"((c)[1]), "+f"((c)[2]), "+f"((c)[3]) \
                 : "r"(a0), "r"(a1), "r"(a2), "r"(a3), "r"(b0), "r"(b1))

// sorted-insert into length-4 top list, (dist, idx) lexicographic
__device__ __forceinline__ void ins4(float* td, int* ti, float d, int i) {
    if (d < td[3] || (d == td[3] && i < ti[3])) {
        td[3] = d; ti[3] = i;
        #pragma unroll
        for (int k = 3; k > 0; k--) {
            bool sw = td[k] < td[k-1] || (td[k] == td[k-1] && ti[k] < ti[k-1]);
            if (sw) {
                float tf = td[k]; td[k] = td[k-1]; td[k-1] = tf;
                int   tt = ti[k]; ti[k] = ti[k-1]; ti[k-1] = tt;
            }
        }
    }
}

// ==================== small kernels ====================
__global__ void k_init() { g_loss = 0.0; }

// identical to round-1 (bit-matching enorm values, used by exact rescore)
__global__ void k_enorm(const float* __restrict__ emb) {
    int k = blockIdx.x, lid = threadIdx.x;
    const float* p = emb + (size_t)k * DIM + lid * 8;
    float4 a = *(const float4*)p;
    float4 b = *(const float4*)(p + 4);
    float s = a.x*a.x; s = fmaf(a.y,a.y,s); s = fmaf(a.z,a.z,s); s = fmaf(a.w,a.w,s);
    s = fmaf(b.x,b.x,s); s = fmaf(b.y,b.y,s); s = fmaf(b.z,b.z,s); s = fmaf(b.w,b.w,s);
    #pragma unroll
    for (int off = 16; off; off >>= 1) s += __shfl_xor_sync(0xffffffffu, s, off);
    if (lid == 0) g_enorm[k] = s;
}

__global__ void k_esplit(const float* __restrict__ emb) {
    int t = blockIdx.x * 256 + threadIdx.x;
    #pragma unroll
    for (int i = 0; i < 4; i++) {
        int id = t * 4 + i;
        g_ehi[id] = __float2half_rn(emb[id] * 1024.0f);
    }
}

// ==================== phase A: top-4 candidate search, single-term fp16 MMA ====================
// chunk j (j = nt*4 + kc): codes [nt*128, +128), k halves [kc*64, +64)
__device__ __forceinline__ void issue_chunk(uint32_t sb, int j, int tid) {
    const int nt = j >> 2, kc = j & 3;
    const uint32_t dst0 = sb + EB_OFF + (uint32_t)(j % 3) * EB_SZ;
    #pragma unroll
    for (int i = 0; i < 4; i++) {
        int g = tid * 4 + i;
        int code = g >> 3, u = g & 7;
        uint32_t dst = dst0 + (uint32_t)(code * 144 + u * 16);
        uint64_t src = (uint64_t)__cvta_generic_to_global(
            g_ehi + (((size_t)(nt * 128 + code)) << 8) + kc * 64 + u * 8);
        asm volatile("cp.async.cg.shared.global [%0], [%1], 16;"
                     :: "r"(dst), "l"(src) : "memory");
    }
    asm volatile("cp.async.commit_group;" ::: "memory");
}

__global__ void __launch_bounds__(256, 2)
k_argmin_mma(const float* __restrict__ z) {
    extern __shared__ char smem[];
    const uint32_t sb = smem_u32(smem);
    const int tid = threadIdx.x;
    const int lane = tid & 31;
    const int warp = tid >> 5;
    const int wm = warp & 1;        // m-group: rows wm*32..+31
    const int wn = warp >> 1;       // n-group: cols wn*32..+31 within 128-code tile

    const int m0 = blockIdx.x * 64;
    const int n_img = m0 >> 10;
    const int hw0 = m0 & (HW - 1);

    issue_chunk(sb, 0, tid);
    issue_chunk(sb, 1, tid);

    // ---------- phase 1: z load + fp16 + approx znorm; stage enorm ----------
    const float* zbase = z + (size_t)n_img * DIM * HW + hw0;
    {
        const int row = tid & 63;
        const int d0  = tid >> 6;          // 0..3
        __half* zh = (__half*)(smem + ZH_OFF);
        float zn = 0.f;
        #pragma unroll 8
        for (int i = 0; i < 64; i++) {
            int d = 4 * i + d0;
            float v = zbase[((size_t)d << 10) + row];
            zn = fmaf(v, v, zn);
            zh[row * 264 + d] = __float2half_rn(v);
        }
        float* tmp = (float*)(smem + CD_OFF);   // 256 f32 scratch
        tmp[tid] = zn;
        float* se = (float*)(smem + EN_OFF);
        #pragma unroll
        for (int i = 0; i < 4; i++) se[tid + 256 * i] = g_enorm[tid + 256 * i];
        __syncthreads();
        if (tid < 64)
            ((float*)(smem + ZN_OFF))[tid] = (tmp[tid] + tmp[tid + 64])
                                           + (tmp[tid + 128] + tmp[tid + 192]);
    }

    // ---------- phase 2: main loop (32 chunks) ----------
    float acc[2][4][4];
    float td[2][2][4]; int ti[2][2][4];
    #pragma unroll
    for (int a = 0; a < 2; a++)
        #pragma unroll
        for (int b = 0; b < 2; b++)
            #pragma unroll
            for (int k = 0; k < 4; k++) { td[a][b][k] = 3.4e38f; ti[a][b][k] = 0x7fffffff; }

    const float* s_zn = (const float*)(smem + ZN_OFF);
    const float* s_en = (const float*)(smem + EN_OFF);

    for (int j = 0; j < 32; j++) {
        const int nt = j >> 2, kc = j & 3;

        if (j < 31) asm volatile("cp.async.wait_group 1;" ::: "memory");
        else        asm volatile("cp.async.wait_group 0;" ::: "memory");
        __syncthreads();
        if (j + 2 < 32) issue_chunk(sb, j + 2, tid);

        if (kc == 0) {
            #pragma unroll
            for (int mt = 0; mt < 2; mt++)
                #pragma unroll
                for (int q = 0; q < 4; q++)
                    #pragma unroll
                    for (int c = 0; c < 4; c++) acc[mt][q][c] = 0.f;
        }

        const uint32_t abase = sb + ZH_OFF;
        const uint32_t bbase = sb + EB_OFF + (uint32_t)(j % 3) * EB_SZ;
        const uint32_t arow  = (uint32_t)(wm * 32 + (lane & 15)) * 528u;
        const uint32_t alanec = (uint32_t)((lane >> 4) * 16);
        const uint32_t brow0 = (uint32_t)(wn * 32 + (lane & 15)) * 144u;
        #pragma unroll
        for (int ks = 0; ks < 4; ks++) {
            const uint32_t akb = (uint32_t)(kc * 128 + ks * 32) + alanec;
            uint32_t a0[4], a1[4];
            LDSM4(a0[0],a0[1],a0[2],a0[3], abase + arow + akb);
            LDSM4(a1[0],a1[1],a1[2],a1[3], abase + arow + 16u*528u + akb);
            const uint32_t bkb = (uint32_t)(ks * 32) + alanec;
            uint32_t br[2][4];
            LDSM4(br[0][0],br[0][1],br[0][2],br[0][3], bbase + brow0 + bkb);
            LDSM4(br[1][0],br[1][1],br[1][2],br[1][3], bbase + brow0 + 16u*144u + bkb);
            #pragma unroll
            for (int qq = 0; qq < 2; qq++) {
                MMA_F16(acc[0][2*qq],   a0[0],a0[1],a0[2],a0[3], br[qq][0], br[qq][2]);
                MMA_F16(acc[0][2*qq+1], a0[0],a0[1],a0[2],a0[3], br[qq][1], br[qq][3]);
                MMA_F16(acc[1][2*qq],   a1[0],a1[1],a1[2],a1[3], br[qq][0], br[qq][2]);
                MMA_F16(acc[1][2*qq+1], a1[0],a1[1],a1[2],a1[3], br[qq][1], br[qq][3]);
            }
        }

        if (kc == 3) {
            // fused epilogue: top-4 candidates per owned row; acc = 1024*dot
            #pragma unroll
            for (int mt = 0; mt < 2; mt++) {
                #pragma unroll
                for (int h = 0; h < 2; h++) {
                    const int row = wm * 32 + mt * 16 + h * 8 + (lane >> 2);
                    const float zn = s_zn[row];
                    #pragma unroll
                    for (int q = 0; q < 4; q++) {
                        #pragma unroll
                        for (int c = 0; c < 2; c++) {
                            const int col = nt * 128 + wn * 32 + q * 8 + (lane & 3) * 2 + c;
                            const float dist =
                                (zn - acc[mt][q][2*h + c] * (1.0f/512.0f)) + s_en[col];
                            ins4(&td[mt][h][0], &ti[mt][h][0], dist, col);
                        }
                    }
                }
            }
        }
    }

    // ---------- candidate merge ----------
    #pragma unroll
    for (int mt = 0; mt < 2; mt++)
        #pragma unroll
        for (int h = 0; h < 2; h++) {
            #pragma unroll
            for (int off = 1; off <= 2; off <<= 1) {
                float od[4]; int oi[4];
                #pragma unroll
                for (int k = 0; k < 4; k++) {
                    od[k] = __shfl_xor_sync(0xffffffffu, td[mt][h][k], off);
                    oi[k] = __shfl_xor_sync(0xffffffffu, ti[mt][h][k], off);
                }
                #pragma unroll
                for (int k = 0; k < 4; k++)
                    ins4(&td[mt][h][0], &ti[mt][h][0], od[k], oi[k]);
            }
        }

    float* cd = (float*)(smem + CD_OFF);
    int*   ci = (int*)(smem + CI_OFF);
    __syncthreads();
    if ((lane & 3) == 0) {
        #pragma unroll
        for (int mt = 0; mt < 2; mt++)
            #pragma unroll
            for (int h = 0; h < 2; h++) {
                int row = wm * 32 + mt * 16 + h * 8 + (lane >> 2);
                #pragma unroll
                for (int k = 0; k < 4; k++) {
                    cd[(row * 4 + wn) * 4 + k] = td[mt][h][k];
                    ci[(row * 4 + wn) * 4 + k] = ti[mt][h][k];
                }
            }
    }
    __syncthreads();
    if (wn == 0 && (lane & 3) == 0) {
        #pragma unroll
        for (int mt = 0; mt < 2; mt++)
            #pragma unroll
            for (int h = 0; h < 2; h++) {
                int row = wm * 32 + mt * 16 + h * 8 + (lane >> 2);
                #pragma unroll
                for (int w2 = 1; w2 < 4; w2++)
                    #pragma unroll
                    for (int k = 0; k < 4; k++)
                        ins4(&td[mt][h][0], &ti[mt][h][0],
                             cd[(row * 4 + w2) * 4 + k], ci[(row * 4 + w2) * 4 + k]);
                #pragma unroll
                for (int k = 0; k < 4; k++)
                    g_cand[(m0 + row) * 4 + k] = ti[mt][h][k];
            }
    }
}

// ==================== phase B: exact fp32 rescore (round-1 bit-exact formulation) ====================
__global__ void __launch_bounds__(256)
k_exact(const float* __restrict__ z, const float* __restrict__ emb,
        float* __restrict__ out_idx) {
    int row = blockIdx.x * 256 + threadIdx.x;
    int n_img = row >> 10, hw = row & 1023;
    const float* zp = z + (size_t)n_img * DIM * HW + hw;

    int4 cn = *(const int4*)&g_cand[row * 4];
    const float4* e0 = (const float4*)(emb + ((size_t)cn.x << 8));
    const float4* e1 = (const float4*)(emb + ((size_t)cn.y << 8));
    const float4* e2 = (const float4*)(emb + ((size_t)cn.z << 8));
    const float4* e3 = (const float4*)(emb + ((size_t)cn.w << 8));

    float a0 = 0.f, a1 = 0.f, a2 = 0.f, a3 = 0.f, zn = 0.f;
    #pragma unroll 4
    for (int d4 = 0; d4 < 64; d4++) {
        float4 v0 = e0[d4], v1 = e1[d4], v2 = e2[d4], v3 = e3[d4];
        float zv;
        zv = zp[(size_t)(d4*4 + 0) << 10];
        zn = fmaf(zv, zv, zn);
        a0 = fmaf(zv, v0.x, a0); a1 = fmaf(zv, v1.x, a1);
        a2 = fmaf(zv, v2.x, a2); a3 = fmaf(zv, v3.x, a3);
        zv = zp[(size_t)(d4*4 + 1) << 10];
        zn = fmaf(zv, zv, zn);
        a0 = fmaf(zv, v0.y, a0); a1 = fmaf(zv, v1.y, a1);
        a2 = fmaf(zv, v2.y, a2); a3 = fmaf(zv, v3.y, a3);
        zv = zp[(size_t)(d4*4 + 2) << 10];
        zn = fmaf(zv, zv, zn);
        a0 = fmaf(zv, v0.z, a0); a1 = fmaf(zv, v1.z, a1);
        a2 = fmaf(zv, v2.z, a2); a3 = fmaf(zv, v3.z, a3);
        zv = zp[(size_t)(d4*4 + 3) << 10];
        zn = fmaf(zv, zv, zn);
        a0 = fmaf(zv, v0.w, a0); a1 = fmaf(zv, v1.w, a1);
        a2 = fmaf(zv, v2.w, a2); a3 = fmaf(zv, v3.w, a3);
    }

    float bd; int bi;
    {
        float t = zn - 2.0f * a0; bd = t + g_enorm[cn.x]; bi = cn.x;
    }
    {
        float t = zn - 2.0f * a1; float d = t + g_enorm[cn.y];
        if (d < bd || (d == bd && cn.y < bi)) { bd = d; bi = cn.y; }
    }
    {
        float t = zn - 2.0f * a2; float d = t + g_enorm[cn.z];
        if (d < bd || (d == bd && cn.z < bi)) { bd = d; bi = cn.z; }
    }
    {
        float t = zn - 2.0f * a3; float d = t + g_enorm[cn.w];
        if (d < bd || (d == bd && cn.w < bi)) { bd = d; bi = cn.w; }
    }

    g_idx[row]   = bi;
    out_idx[row] = (float)bi;
}

// ==================== output + loss ====================
__global__ void __launch_bounds__(256)
k_out(const float* __restrict__ z, const float* __restrict__ emb,
      float* __restrict__ out_zq) {
    int t    = blockIdx.x * 256 + threadIdx.x;
    int hw   = t & 1023;
    int rest = t >> 10;
    int db   = (rest & 63) << 2;
    int n    = rest >> 6;

    int idx = g_idx[(n << 10) + hw];
    float4 e = *(const float4*)&emb[(size_t)idx * DIM + db];

    size_t zb = (((size_t)n * DIM + db) << 10) + hw;
    float z0 = z[zb], z1 = z[zb + 1024], z2 = z[zb + 2048], z3 = z[zb + 3072];

    out_zq[zb]        = z0 + (e.x - z0);
    out_zq[zb + 1024] = z1 + (e.y - z1);
    out_zq[zb + 2048] = z2 + (e.z - z2);
    out_zq[zb + 3072] = z3 + (e.w - z3);

    float d0 = z0 - e.x, d1 = z1 - e.y, d2 = z2 - e.z, d3 = z3 - e.w;
    float sq = d0*d0 + d1*d1 + d2*d2 + d3*d3;

    #pragma unroll
    for (int off = 16; off; off >>= 1) sq += __shfl_xor_sync(0xffffffffu, sq, off);

    __shared__ float wsum[8];
    int wid = threadIdx.x >> 5, lid = threadIdx.x & 31;
    if (lid == 0) wsum[wid] = sq;
    __syncthreads();
    if (threadIdx.x == 0) {
        float s = 0.f;
        #pragma unroll
        for (int w = 0; w < 8; w++) s += wsum[w];
        atomicAdd(&g_loss, (double)s);
    }
}

__global__ void k_fin(float* __restrict__ out_loss) {
    float m = (float)(g_loss / (double)ZQ_ELEMS);
    out_loss[0] = 0.02f * m + m;
}

extern "C" void kernel_launch(void* const* d_in, const int* in_sizes, int n_in,
                              void* d_out, int out_size) {
    const float* z   = (const float*)d_in[0];
    const float* emb = (const float*)d_in[1];
    float* out      = (float*)d_out;
    float* out_zq   = out;
    float* out_idx  = out + ZQ_ELEMS;
    float* out_loss = out + ZQ_ELEMS + MTOT;

    cudaFuncSetAttribute(k_argmin_mma, cudaFuncAttributeMaxDynamicSharedMemorySize, SMEM_ARG);

    k_init      <<<1, 1>>>();
    k_enorm     <<<KCODES, 32>>>(emb);
    k_esplit    <<<256, 256>>>(emb);
    k_argmin_mma<<<MTOT / 64, 256, SMEM_ARG>>>(z);
    k_exact     <<<MTOT / 256, 256>>>(z, emb, out_idx);
    k_out       <<<ZQ_ELEMS / (256 * 4), 256>>>(z, emb, out_zq);
    k_fin       <<<1, 1>>>(out_loss);
}